// round 2
// baseline (speedup 1.0000x reference)
#include <cuda_runtime.h>
#include <cuda_bf16.h>

// ---------------------------------------------------------------------------
// BEVHDMapFusionNet: conv(bev+ego) -> Q ; conv(hd)+resize(front) -> KV ;
// 4-head cross attention (Nq=Nk=1024, d=32) ; O-proj ; conv(fused+ego) -> out
// B*T = 8 images, spatial 32x32, F=128 channels.
// ---------------------------------------------------------------------------

#define BT 8
#define HW 1024

__device__ float g_bev_feat[BT * 128 * HW];  // NCHW
__device__ float g_kv[BT * 192 * HW];        // ch 0..127 hd_feat, 128..191 front resized
__device__ float g_q[BT * HW * 128];         // row-major [n][o]
__device__ float g_k[BT * HW * 128];
__device__ float g_v[BT * HW * 128];
__device__ float g_attn[BT * HW * 128];
__device__ float g_fused[BT * 128 * HW];     // NCHW (pre-conv_out input)

// ---------------------------------------------------------------------------
// Direct 3x3 SAME conv + bias + relu. Optional 16 ego channels appended to the
// input (spatially constant, zero-padded at borders like any other channel).
// Block: 256 threads -> 32 oc x (8y x 32x) tile. Loops input channels in
// chunks of 16 staged in shared memory. Weight reads are float4 broadcasts.
// Grid: (BT, 128/32, 32/8) = (8,4,4) = 128 blocks.
// ---------------------------------------------------------------------------
template<int CIN_MAIN, int CIN_TOT>
__global__ void __launch_bounds__(256) conv3x3_relu_kernel(
    const float* __restrict__ in, const float* __restrict__ ego,
    const float* __restrict__ w, const float* __restrict__ bias,
    float* __restrict__ out, int out_ctot)
{
    __shared__ float s_in[16][10][34];   // 16 ic x (8+2 halo rows) x (32+2 halo cols)
    __shared__ float s_w[16][9][32];     // [ic][k][oc]

    const int bt  = blockIdx.x;
    const int oc0 = blockIdx.y << 5;
    const int y0  = blockIdx.z << 3;
    const int tid = threadIdx.x;
    const int tx  = tid & 31, ty = tid >> 5;

    float acc[32];
#pragma unroll
    for (int i = 0; i < 32; i++) acc[i] = 0.f;

    for (int c0 = 0; c0 < CIN_TOT; c0 += 16) {
        // stage input tile (zero padded)
        for (int idx = tid; idx < 16 * 10 * 34; idx += 256) {
            int ic  = idx / 340;
            int rem = idx - ic * 340;
            int yy  = rem / 34, xx = rem - yy * 34;
            int gy  = y0 + yy - 1, gx = xx - 1;
            int c   = c0 + ic;
            float v = 0.f;
            if ((unsigned)gy < 32u && (unsigned)gx < 32u) {
                if (CIN_MAIN == CIN_TOT || c < CIN_MAIN)
                    v = in[((bt * CIN_MAIN + c) << 10) + (gy << 5) + gx];
                else
                    v = ego[(bt << 4) + (c - CIN_MAIN)];
            }
            s_in[ic][yy][xx] = v;
        }
        // stage weights transposed to [ic][k][oc]
        for (int idx = tid; idx < 16 * 9 * 32; idx += 256) {
            int oc  = idx & 31;
            int rem = idx >> 5;
            int ic  = rem / 9, k = rem - ic * 9;
            s_w[ic][k][oc] = w[((oc0 + oc) * CIN_TOT + c0 + ic) * 9 + k];
        }
        __syncthreads();

#pragma unroll 1
        for (int ic = 0; ic < 16; ic++) {
            float v[9];
#pragma unroll
            for (int ky = 0; ky < 3; ky++)
#pragma unroll
                for (int kx = 0; kx < 3; kx++)
                    v[ky * 3 + kx] = s_in[ic][ty + ky][tx + kx];
#pragma unroll
            for (int k = 0; k < 9; k++) {
                const float4* wp = (const float4*)s_w[ic][k];
                float vk = v[k];
#pragma unroll
                for (int q8 = 0; q8 < 8; q8++) {
                    float4 w4 = wp[q8];
                    acc[q8 * 4 + 0] = fmaf(vk, w4.x, acc[q8 * 4 + 0]);
                    acc[q8 * 4 + 1] = fmaf(vk, w4.y, acc[q8 * 4 + 1]);
                    acc[q8 * 4 + 2] = fmaf(vk, w4.z, acc[q8 * 4 + 2]);
                    acc[q8 * 4 + 3] = fmaf(vk, w4.w, acc[q8 * 4 + 3]);
                }
            }
        }
        __syncthreads();
    }

    const int y = y0 + ty;
#pragma unroll
    for (int oc = 0; oc < 32; oc++) {
        float r = acc[oc] + bias[oc0 + oc];
        out[((bt * out_ctot + oc0 + oc) << 10) + (y << 5) + tx] = fmaxf(r, 0.f);
    }
}

// ---------------------------------------------------------------------------
// Bilinear 16x16 -> 32x32 resize matching jax.image.resize (renormalized
// triangle kernel == index-clamped bilerp, src = dst*0.5 - 0.25).
// Writes channels 128..191 of g_kv.
// ---------------------------------------------------------------------------
__global__ void __launch_bounds__(256) resize_kernel(
    const float* __restrict__ front, float* __restrict__ kv)
{
    int idx = blockIdx.x * 256 + threadIdx.x;   // 8*64*1024 total
    if (idx >= BT * 64 * HW) return;
    int x = idx & 31, y = (idx >> 5) & 31, c = (idx >> 10) & 63, bt = idx >> 16;
    float fy = y * 0.5f - 0.25f, fx = x * 0.5f - 0.25f;
    int y0 = (int)floorf(fy), x0 = (int)floorf(fx);
    float wy = fy - (float)y0, wx = fx - (float)x0;
    int y0c = max(y0, 0), y1c = min(y0 + 1, 15);
    int x0c = max(x0, 0), x1c = min(x0 + 1, 15);
    const float* base = &front[(bt * 64 + c) << 8];
    float v00 = base[(y0c << 4) + x0c], v01 = base[(y0c << 4) + x1c];
    float v10 = base[(y1c << 4) + x0c], v11 = base[(y1c << 4) + x1c];
    float v = (1.f - wy) * ((1.f - wx) * v00 + wx * v01)
            + wy * ((1.f - wx) * v10 + wx * v11);
    kv[((bt * 192 + 128 + c) << 10) + (y << 5) + x] = v;
}

// ---------------------------------------------------------------------------
// GEMM: out[bt][n][o] = sum_c A(c,n) * W[o][c]  (M=8192, N=128, K runtime).
// AROW=false: A is channel-major NCHW ([bt][c][n], coalesced in n).
// AROW=true:  A is row-major [bt][n][c] (attention output).
// TOUT=true:  store transposed to NCHW [bt][o][n] with bias (O-projection).
// 128x128 tile, 256 threads, 8x8 microtile per thread.
// ---------------------------------------------------------------------------
template<bool AROW, bool TOUT>
__device__ __forceinline__ void gemm128_body(
    const float* __restrict__ A, const float* __restrict__ W,
    const float* __restrict__ bias, float* __restrict__ out, int K)
{
    __shared__ float s_A[16][132];   // padded: 2-way max conflict on transposed stores
    __shared__ float s_B[16][128];

    const int tid  = threadIdx.x;
    const int mblk = blockIdx.x;
    const int bt   = mblk >> 3;
    const int nloc = (mblk & 7) << 7;
    const int tm = tid & 15, tn = tid >> 4;
    const int m0 = tm << 3, o0 = tn << 3;

    float acc[8][8];
#pragma unroll
    for (int i = 0; i < 8; i++)
#pragma unroll
        for (int j = 0; j < 8; j++) acc[i][j] = 0.f;

    for (int c0 = 0; c0 < K; c0 += 16) {
        if (AROW) {
            for (int idx = tid; idx < 2048; idx += 256) {
                int kk = idx & 15, m = idx >> 4;
                s_A[kk][m] = A[(bt * 1024 + nloc + m) * K + c0 + kk];
            }
        } else {
            for (int idx = tid; idx < 512; idx += 256) {
                int kk = idx >> 5, j = idx & 31;
                float4 t = *(const float4*)&A[((bt * K + c0 + kk) << 10) + nloc + (j << 2)];
                *(float4*)&s_A[kk][j << 2] = t;
            }
        }
        for (int idx = tid; idx < 2048; idx += 256) {
            int o = idx & 127, kk = idx >> 7;
            s_B[kk][o] = W[o * K + c0 + kk];
        }
        __syncthreads();

#pragma unroll
        for (int kk = 0; kk < 16; kk++) {
            float4 a0 = *(const float4*)&s_A[kk][m0];
            float4 a1 = *(const float4*)&s_A[kk][m0 + 4];
            float4 b0 = *(const float4*)&s_B[kk][o0];
            float4 b1 = *(const float4*)&s_B[kk][o0 + 4];
            float a[8] = {a0.x, a0.y, a0.z, a0.w, a1.x, a1.y, a1.z, a1.w};
            float b[8] = {b0.x, b0.y, b0.z, b0.w, b1.x, b1.y, b1.z, b1.w};
#pragma unroll
            for (int i = 0; i < 8; i++)
#pragma unroll
                for (int j = 0; j < 8; j++)
                    acc[i][j] = fmaf(a[i], b[j], acc[i][j]);
        }
        __syncthreads();
    }

    if (TOUT) {
#pragma unroll
        for (int j = 0; j < 8; j++) {
            float bb = bias ? bias[o0 + j] : 0.f;
#pragma unroll
            for (int i = 0; i < 8; i += 4) {
                float4 t = {acc[i][j] + bb, acc[i + 1][j] + bb,
                            acc[i + 2][j] + bb, acc[i + 3][j] + bb};
                *(float4*)&out[((bt << 7) + o0 + j) * 1024 + nloc + m0 + i] = t;
            }
        }
    } else {
#pragma unroll
        for (int i = 0; i < 8; i++)
#pragma unroll
            for (int j = 0; j < 8; j += 4) {
                float4 t = {acc[i][j], acc[i][j + 1], acc[i][j + 2], acc[i][j + 3]};
                *(float4*)&out[(bt * 1024 + nloc + m0 + i) * 128 + o0 + j] = t;
            }
    }
}

__global__ void __launch_bounds__(256) qkv_kernel(
    const float* __restrict__ bevf, const float* __restrict__ kv,
    const float* __restrict__ wq, const float* __restrict__ wk,
    const float* __restrict__ wv,
    float* __restrict__ q, float* __restrict__ k, float* __restrict__ v)
{
    if (blockIdx.y == 0)      gemm128_body<false, false>(bevf, wq, nullptr, q, 128);
    else if (blockIdx.y == 1) gemm128_body<false, false>(kv,   wk, nullptr, k, 192);
    else                      gemm128_body<false, false>(kv,   wv, nullptr, v, 192);
}

__global__ void __launch_bounds__(256) oproj_kernel(
    const float* __restrict__ attn, const float* __restrict__ wo,
    const float* __restrict__ bo, float* __restrict__ fused)
{
    gemm128_body<true, true>(attn, wo, bo, fused, 128);
}

// ---------------------------------------------------------------------------
// Flash attention, d=32, Nq=Nk=1024, 4 heads.
// Block: 128 threads, each thread owns one full query row (Q and O in regs).
// K/V staged in smem 32 rows at a time; row reads are float4 broadcasts.
// Grid: (8 qtiles, 4 heads, 8 bt) = 256 blocks.
// ---------------------------------------------------------------------------
__global__ void __launch_bounds__(128) attention_kernel(
    const float* __restrict__ Q, const float* __restrict__ K,
    const float* __restrict__ V, float* __restrict__ O)
{
    __shared__ float sK[32][32];
    __shared__ float sV[32][32];
    const int qt = blockIdx.x, h = blockIdx.y, bt = blockIdx.z;
    const int r = threadIdx.x;
    const int n = (qt << 7) + r;
    const float scale = 0.17677669529663687f;   // 32^-0.5

    float q[32];
    {
        const float4* qp = (const float4*)&Q[(bt * 1024 + n) * 128 + (h << 5)];
#pragma unroll
        for (int i = 0; i < 8; i++) {
            float4 t = qp[i];
            q[4 * i]     = t.x * scale; q[4 * i + 1] = t.y * scale;
            q[4 * i + 2] = t.z * scale; q[4 * i + 3] = t.w * scale;
        }
    }
    float o[32];
#pragma unroll
    for (int i = 0; i < 32; i++) o[i] = 0.f;
    float m_run = -1e30f, l_run = 0.f;

    for (int kt = 0; kt < 1024; kt += 32) {
        for (int i = r; i < 256; i += 128) {
            int kk = i >> 3, j = i & 7;
            ((float4*)sK[kk])[j] =
                ((const float4*)&K[((bt << 10) + kt + kk) * 128 + (h << 5)])[j];
            ((float4*)sV[kk])[j] =
                ((const float4*)&V[((bt << 10) + kt + kk) * 128 + (h << 5)])[j];
        }
        __syncthreads();

        float s[32];
#pragma unroll 4
        for (int kk = 0; kk < 32; kk++) {
            const float4* kp = (const float4*)sK[kk];
            float a = 0.f;
#pragma unroll
            for (int i = 0; i < 8; i++) {
                float4 t = kp[i];
                a = fmaf(q[4 * i], t.x, a);     a = fmaf(q[4 * i + 1], t.y, a);
                a = fmaf(q[4 * i + 2], t.z, a); a = fmaf(q[4 * i + 3], t.w, a);
            }
            s[kk] = a;
        }
        float m_new = m_run;
#pragma unroll
        for (int kk = 0; kk < 32; kk++) m_new = fmaxf(m_new, s[kk]);
        float corr = __expf(m_run - m_new);
        float lad = 0.f;
#pragma unroll
        for (int kk = 0; kk < 32; kk++) { s[kk] = __expf(s[kk] - m_new); lad += s[kk]; }
        l_run = l_run * corr + lad;
        m_run = m_new;
#pragma unroll
        for (int i = 0; i < 32; i++) o[i] *= corr;
#pragma unroll 4
        for (int kk = 0; kk < 32; kk++) {
            const float4* vp = (const float4*)sV[kk];
            float p = s[kk];
#pragma unroll
            for (int i = 0; i < 8; i++) {
                float4 t = vp[i];
                o[4 * i]     = fmaf(p, t.x, o[4 * i]);
                o[4 * i + 1] = fmaf(p, t.y, o[4 * i + 1]);
                o[4 * i + 2] = fmaf(p, t.z, o[4 * i + 2]);
                o[4 * i + 3] = fmaf(p, t.w, o[4 * i + 3]);
            }
        }
        __syncthreads();
    }

    float inv = 1.f / l_run;
    float4* op = (float4*)&O[(bt * 1024 + n) * 128 + (h << 5)];
#pragma unroll
    for (int i = 0; i < 8; i++) {
        float4 t = {o[4 * i] * inv, o[4 * i + 1] * inv,
                    o[4 * i + 2] * inv, o[4 * i + 3] * inv};
        op[i] = t;
    }
}

// ---------------------------------------------------------------------------
extern "C" void kernel_launch(void* const* d_in, const int* in_sizes, int n_in,
                              void* d_out, int out_size)
{
    const float* bev   = (const float*)d_in[0];
    const float* hd    = (const float*)d_in[1];
    const float* ego   = (const float*)d_in[2];
    const float* front = (const float*)d_in[3];
    const float* w_bev = (const float*)d_in[4];
    const float* b_bev = (const float*)d_in[5];
    const float* w_hd  = (const float*)d_in[6];
    const float* b_hd  = (const float*)d_in[7];
    const float* wq    = (const float*)d_in[8];
    const float* wk    = (const float*)d_in[9];
    const float* wv    = (const float*)d_in[10];
    const float* wo    = (const float*)d_in[11];
    const float* bo    = (const float*)d_in[12];
    const float* w_out = (const float*)d_in[13];
    const float* b_out = (const float*)d_in[14];
    float* out = (float*)d_out;

    float *bevf, *kv, *q, *k, *v, *attn, *fused;
    cudaGetSymbolAddress((void**)&bevf,  g_bev_feat);
    cudaGetSymbolAddress((void**)&kv,    g_kv);
    cudaGetSymbolAddress((void**)&q,     g_q);
    cudaGetSymbolAddress((void**)&k,     g_k);
    cudaGetSymbolAddress((void**)&v,     g_v);
    cudaGetSymbolAddress((void**)&attn,  g_attn);
    cudaGetSymbolAddress((void**)&fused, g_fused);

    dim3 cgrid(BT, 4, 4);
    conv3x3_relu_kernel<128, 144><<<cgrid, 256>>>(bev, ego, w_bev, b_bev, bevf, 128);
    conv3x3_relu_kernel<64, 64><<<cgrid, 256>>>(hd, nullptr, w_hd, b_hd, kv, 192);
    resize_kernel<<<(BT * 64 * HW) / 256, 256>>>(front, kv);
    qkv_kernel<<<dim3(64, 3), 256>>>(bevf, kv, wq, wk, wv, q, k, v);
    attention_kernel<<<dim3(8, 4, 8), 128>>>(q, k, v, attn);
    oproj_kernel<<<64, 256>>>(attn, wo, bo, fused);
    conv3x3_relu_kernel<128, 144><<<cgrid, 256>>>(fused, ego, w_out, b_out, out, 128);
}

// round 4
// speedup vs baseline: 1.0269x; 1.0269x over previous
#include <cuda_runtime.h>
#include <cuda_bf16.h>

// ---------------------------------------------------------------------------
// BEVHDMapFusionNet — round 3: packed fp32 (fma.rn.f32x2) everywhere.
// ---------------------------------------------------------------------------

#define BT 8
#define HW 1024

typedef unsigned long long u64;

__device__ __forceinline__ u64 pack2(float lo, float hi) {
    u64 r; asm("mov.b64 %0, {%1, %2};" : "=l"(r) : "f"(lo), "f"(hi)); return r;
}
__device__ __forceinline__ void unpack2(u64 v, float& lo, float& hi) {
    asm("mov.b64 {%0, %1}, %2;" : "=f"(lo), "=f"(hi) : "l"(v));
}
__device__ __forceinline__ void ffma2(u64& d, u64 a, u64 b) {
    asm("fma.rn.f32x2 %0, %1, %2, %0;" : "+l"(d) : "l"(a), "l"(b));
}
__device__ __forceinline__ u64 mul2(u64 a, u64 b) {
    u64 r; asm("mul.rn.f32x2 %0, %1, %2;" : "=l"(r) : "l"(a), "l"(b)); return r;
}
__device__ __forceinline__ u64 add2(u64 a, u64 b) {
    u64 r; asm("add.rn.f32x2 %0, %1, %2;" : "=l"(r) : "l"(a), "l"(b)); return r;
}

__device__ float g_bev_feat[BT * 128 * HW];  // NCHW
__device__ float g_kv[BT * 192 * HW];        // ch 0..127 hd_feat, 128..191 front resized
__device__ float g_q[BT * HW * 128];         // row-major [n][o]
__device__ float g_k[BT * HW * 128];
__device__ float g_v[BT * HW * 128];
__device__ float g_attn[BT * HW * 128];
__device__ float g_fused[BT * 128 * HW];     // NCHW

// ---------------------------------------------------------------------------
// Direct 3x3 SAME conv + bias + relu, fp32x2-packed over output channels.
// Block: 256 threads = 32x * 8y pixels, 16 oc per thread (8 f32x2 accs).
// Grid: (BT, 128/16 oc groups, 32/8 y tiles) = (8, 8, 4) = 256 blocks.
// ---------------------------------------------------------------------------
template<int CIN_MAIN, int CIN_TOT>
__global__ void __launch_bounds__(256) conv3x3_relu_kernel(
    const float* __restrict__ in, const float* __restrict__ ego,
    const float* __restrict__ w, const float* __restrict__ bias,
    float* __restrict__ out, int out_ctot)
{
    __shared__ __align__(16) float s_in[16][10][34];  // ic x (8+2) x (32+2)
    __shared__ __align__(16) float s_w[16][9][16];    // [ic][k][oc]

    const int bt  = blockIdx.x;
    const int oc0 = blockIdx.y << 4;
    const int y0  = blockIdx.z << 3;
    const int tid = threadIdx.x;
    const int tx  = tid & 31, ty = tid >> 5;

    u64 acc2[8];
#pragma unroll
    for (int i = 0; i < 8; i++) acc2[i] = 0ull;

    for (int c0 = 0; c0 < CIN_TOT; c0 += 16) {
        // stage input tile (zero padded)
        for (int idx = tid; idx < 16 * 10 * 34; idx += 256) {
            int ic  = idx / 340;
            int rem = idx - ic * 340;
            int yy  = rem / 34, xx = rem - yy * 34;
            int gy  = y0 + yy - 1, gx = xx - 1;
            int c   = c0 + ic;
            float v = 0.f;
            if ((unsigned)gy < 32u && (unsigned)gx < 32u) {
                if (CIN_MAIN == CIN_TOT || c < CIN_MAIN)
                    v = in[((bt * CIN_MAIN + c) << 10) + (gy << 5) + gx];
                else
                    v = ego[(bt << 4) + (c - CIN_MAIN)];
            }
            s_in[ic][yy][xx] = v;
        }
        // stage weights transposed to [ic][k][oc]
        for (int idx = tid; idx < 16 * 9 * 16; idx += 256) {
            int oc  = idx & 15;
            int rem = idx >> 4;
            int ic  = rem / 9, k = rem - ic * 9;
            s_w[ic][k][oc] = w[((oc0 + oc) * CIN_TOT + c0 + ic) * 9 + k];
        }
        __syncthreads();

#pragma unroll 2
        for (int ic = 0; ic < 16; ic++) {
            float v[9];
#pragma unroll
            for (int ky = 0; ky < 3; ky++)
#pragma unroll
                for (int kx = 0; kx < 3; kx++)
                    v[ky * 3 + kx] = s_in[ic][ty + ky][tx + kx];
#pragma unroll
            for (int k = 0; k < 9; k++) {
                u64 vk2 = pack2(v[k], v[k]);
                const ulonglong2* wp = (const ulonglong2*)s_w[ic][k];
                ulonglong2 w01 = wp[0], w23 = wp[1], w45 = wp[2], w67 = wp[3];
                ffma2(acc2[0], vk2, w01.x); ffma2(acc2[1], vk2, w01.y);
                ffma2(acc2[2], vk2, w23.x); ffma2(acc2[3], vk2, w23.y);
                ffma2(acc2[4], vk2, w45.x); ffma2(acc2[5], vk2, w45.y);
                ffma2(acc2[6], vk2, w67.x); ffma2(acc2[7], vk2, w67.y);
            }
        }
        __syncthreads();
    }

    const int y = y0 + ty;
#pragma unroll
    for (int p = 0; p < 8; p++) {
        float f0, f1;
        unpack2(acc2[p], f0, f1);
        int oc = oc0 + 2 * p;
        float r0 = fmaxf(f0 + bias[oc], 0.f);
        float r1 = fmaxf(f1 + bias[oc + 1], 0.f);
        out[((bt * out_ctot + oc) << 10) + (y << 5) + tx] = r0;
        out[((bt * out_ctot + oc + 1) << 10) + (y << 5) + tx] = r1;
    }
}

// ---------------------------------------------------------------------------
// Bilinear 16x16 -> 32x32 resize matching jax.image.resize
// (index-clamped bilerp, src = dst*0.5 - 0.25). Writes ch 128..191 of g_kv.
// ---------------------------------------------------------------------------
__global__ void __launch_bounds__(256) resize_kernel(
    const float* __restrict__ front, float* __restrict__ kv)
{
    int idx = blockIdx.x * 256 + threadIdx.x;
    if (idx >= BT * 64 * HW) return;
    int x = idx & 31, y = (idx >> 5) & 31, c = (idx >> 10) & 63, bt = idx >> 16;
    float fy = y * 0.5f - 0.25f, fx = x * 0.5f - 0.25f;
    int y0 = (int)floorf(fy), x0 = (int)floorf(fx);
    float wy = fy - (float)y0, wx = fx - (float)x0;
    int y0c = max(y0, 0), y1c = min(y0 + 1, 15);
    int x0c = max(x0, 0), x1c = min(x0 + 1, 15);
    const float* base = &front[(bt * 64 + c) << 8];
    float v00 = base[(y0c << 4) + x0c], v01 = base[(y0c << 4) + x1c];
    float v10 = base[(y1c << 4) + x0c], v11 = base[(y1c << 4) + x1c];
    float v = (1.f - wy) * ((1.f - wx) * v00 + wx * v01)
            + wy * ((1.f - wx) * v10 + wx * v11);
    kv[((bt * 192 + 128 + c) << 10) + (y << 5) + x] = v;
}

// ---------------------------------------------------------------------------
// GEMM: out[bt][n][o] = sum_c A(c,n) * W[o][c]  (M=8192, N=128).
// 128x128 tile, 256 threads, 8m x 8n microtile, f32x2 pairs along n.
// ---------------------------------------------------------------------------
template<bool AROW, bool TOUT, int K>
__device__ __forceinline__ void gemm128_body(
    const float* __restrict__ A, const float* __restrict__ W,
    const float* __restrict__ bias, float* __restrict__ out)
{
    __shared__ __align__(16) float s_A[16][132];
    __shared__ __align__(16) float s_B[16][128];

    const int tid  = threadIdx.x;
    const int mblk = blockIdx.x;
    const int bt   = mblk >> 3;
    const int nloc = (mblk & 7) << 7;
    const int tm = tid & 15, tn = tid >> 4;
    const int m0 = tm << 3, o0 = tn << 3;

    u64 acc2[8][4];
#pragma unroll
    for (int i = 0; i < 8; i++)
#pragma unroll
        for (int j = 0; j < 4; j++) acc2[i][j] = 0ull;

    for (int c0 = 0; c0 < K; c0 += 16) {
        if (AROW) {
            for (int idx = tid; idx < 2048; idx += 256) {
                int kk = idx & 15, m = idx >> 4;
                s_A[kk][m] = A[(bt * 1024 + nloc + m) * K + c0 + kk];
            }
        } else {
            for (int idx = tid; idx < 512; idx += 256) {
                int kk = idx >> 5, j = idx & 31;
                float4 t = *(const float4*)&A[((bt * K + c0 + kk) << 10) + nloc + (j << 2)];
                *(float4*)&s_A[kk][j << 2] = t;
            }
        }
        for (int idx = tid; idx < 2048; idx += 256) {
            int o = idx & 127, kk = idx >> 7;
            s_B[kk][o] = W[o * K + c0 + kk];
        }
        __syncthreads();

#pragma unroll
        for (int kk = 0; kk < 16; kk++) {
            float4 a0 = *(const float4*)&s_A[kk][m0];
            float4 a1 = *(const float4*)&s_A[kk][m0 + 4];
            ulonglong2 b01 = *(const ulonglong2*)&s_B[kk][o0];
            ulonglong2 b23 = *(const ulonglong2*)&s_B[kk][o0 + 4];
            u64 ap[8];
            ap[0] = pack2(a0.x, a0.x); ap[1] = pack2(a0.y, a0.y);
            ap[2] = pack2(a0.z, a0.z); ap[3] = pack2(a0.w, a0.w);
            ap[4] = pack2(a1.x, a1.x); ap[5] = pack2(a1.y, a1.y);
            ap[6] = pack2(a1.z, a1.z); ap[7] = pack2(a1.w, a1.w);
#pragma unroll
            for (int i = 0; i < 8; i++) {
                ffma2(acc2[i][0], ap[i], b01.x);
                ffma2(acc2[i][1], ap[i], b01.y);
                ffma2(acc2[i][2], ap[i], b23.x);
                ffma2(acc2[i][3], ap[i], b23.y);
            }
        }
        __syncthreads();
    }

    if (TOUT) {
        float f[8][8];
#pragma unroll
        for (int i = 0; i < 8; i++)
#pragma unroll
            for (int jp = 0; jp < 4; jp++)
                unpack2(acc2[i][jp], f[i][2 * jp], f[i][2 * jp + 1]);
#pragma unroll
        for (int j = 0; j < 8; j++) {
            float bb = bias ? bias[o0 + j] : 0.f;
#pragma unroll
            for (int i = 0; i < 8; i += 4) {
                float4 t = {f[i][j] + bb, f[i + 1][j] + bb,
                            f[i + 2][j] + bb, f[i + 3][j] + bb};
                *(float4*)&out[((bt << 7) + o0 + j) * 1024 + nloc + m0 + i] = t;
            }
        }
    } else {
#pragma unroll
        for (int i = 0; i < 8; i++) {
            ulonglong2 t0 = {acc2[i][0], acc2[i][1]};
            ulonglong2 t1 = {acc2[i][2], acc2[i][3]};
            ulonglong2* op = (ulonglong2*)&out[(bt * 1024 + nloc + m0 + i) * 128 + o0];
            op[0] = t0; op[1] = t1;
        }
    }
}

__global__ void __launch_bounds__(256) qkv_kernel(
    const float* __restrict__ bevf, const float* __restrict__ kv,
    const float* __restrict__ wq, const float* __restrict__ wk,
    const float* __restrict__ wv,
    float* __restrict__ q, float* __restrict__ k, float* __restrict__ v)
{
    if (blockIdx.y == 0)      gemm128_body<false, false, 128>(bevf, wq, nullptr, q);
    else if (blockIdx.y == 1) gemm128_body<false, false, 192>(kv,   wk, nullptr, k);
    else                      gemm128_body<false, false, 192>(kv,   wv, nullptr, v);
}

__global__ void __launch_bounds__(256) oproj_kernel(
    const float* __restrict__ attn, const float* __restrict__ wo,
    const float* __restrict__ bo, float* __restrict__ fused)
{
    gemm128_body<true, true, 128>(attn, wo, bo, fused);
}

// ---------------------------------------------------------------------------
// Flash attention, d=32, Nq=Nk=1024, 4 heads, fp32x2-packed.
// Block: 128 threads, each owns one query row. Grid: (8, 4, 8) = 256 blocks.
// ---------------------------------------------------------------------------
__global__ void __launch_bounds__(128) attention_kernel(
    const float* __restrict__ Q, const float* __restrict__ K,
    const float* __restrict__ V, float* __restrict__ O)
{
    __shared__ __align__(16) float sK[32][32];
    __shared__ __align__(16) float sV[32][32];
    const int qt = blockIdx.x, h = blockIdx.y, bt = blockIdx.z;
    const int r = threadIdx.x;
    const int n = (qt << 7) + r;
    const float scale = 0.17677669529663687f;   // 32^-0.5

    u64 q2[16];
    {
        u64 sc2 = pack2(scale, scale);
        const ulonglong2* qp = (const ulonglong2*)&Q[(bt * 1024 + n) * 128 + (h << 5)];
#pragma unroll
        for (int i = 0; i < 8; i++) {
            ulonglong2 t = qp[i];
            q2[2 * i]     = mul2(t.x, sc2);
            q2[2 * i + 1] = mul2(t.y, sc2);
        }
    }
    u64 o2[16];
#pragma unroll
    for (int i = 0; i < 16; i++) o2[i] = 0ull;
    float m_run = -1e30f, l_run = 0.f;

    for (int kt = 0; kt < 1024; kt += 32) {
        for (int i = r; i < 256; i += 128) {
            int kk = i >> 3, j = i & 7;
            ((float4*)sK[kk])[j] =
                ((const float4*)&K[((bt << 10) + kt + kk) * 128 + (h << 5)])[j];
            ((float4*)sV[kk])[j] =
                ((const float4*)&V[((bt << 10) + kt + kk) * 128 + (h << 5)])[j];
        }
        __syncthreads();

        float s[32];
#pragma unroll 4
        for (int kk = 0; kk < 32; kk++) {
            const ulonglong2* kp = (const ulonglong2*)sK[kk];
            u64 acc0 = 0ull, acc1 = 0ull;
#pragma unroll
            for (int i = 0; i < 8; i++) {
                ulonglong2 t = kp[i];
                ffma2(acc0, q2[2 * i], t.x);
                ffma2(acc1, q2[2 * i + 1], t.y);
            }
            u64 accs = add2(acc0, acc1);
            float lo, hi;
            unpack2(accs, lo, hi);
            s[kk] = lo + hi;
        }
        float m_new = m_run;
#pragma unroll
        for (int kk = 0; kk < 32; kk++) m_new = fmaxf(m_new, s[kk]);
        float corr = __expf(m_run - m_new);
        float lad = 0.f;
#pragma unroll
        for (int kk = 0; kk < 32; kk++) { s[kk] = __expf(s[kk] - m_new); lad += s[kk]; }
        l_run = l_run * corr + lad;
        m_run = m_new;
        u64 corr2 = pack2(corr, corr);
#pragma unroll
        for (int i = 0; i < 16; i++) o2[i] = mul2(o2[i], corr2);
#pragma unroll 4
        for (int kk = 0; kk < 32; kk++) {
            const ulonglong2* vp = (const ulonglong2*)sV[kk];
            u64 p2 = pack2(s[kk], s[kk]);
#pragma unroll
            for (int i = 0; i < 8; i++) {
                ulonglong2 t = vp[i];
                ffma2(o2[2 * i], p2, t.x);
                ffma2(o2[2 * i + 1], p2, t.y);
            }
        }
        __syncthreads();
    }

    float inv = 1.f / l_run;
    u64 inv2 = pack2(inv, inv);
    ulonglong2* op = (ulonglong2*)&O[(bt * 1024 + n) * 128 + (h << 5)];
#pragma unroll
    for (int i = 0; i < 8; i++) {
        ulonglong2 t = {mul2(o2[2 * i], inv2), mul2(o2[2 * i + 1], inv2)};
        op[i] = t;
    }
}

// ---------------------------------------------------------------------------
extern "C" void kernel_launch(void* const* d_in, const int* in_sizes, int n_in,
                              void* d_out, int out_size)
{
    const float* bev   = (const float*)d_in[0];
    const float* hd    = (const float*)d_in[1];
    const float* ego   = (const float*)d_in[2];
    const float* front = (const float*)d_in[3];
    const float* w_bev = (const float*)d_in[4];
    const float* b_bev = (const float*)d_in[5];
    const float* w_hd  = (const float*)d_in[6];
    const float* b_hd  = (const float*)d_in[7];
    const float* wq    = (const float*)d_in[8];
    const float* wk    = (const float*)d_in[9];
    const float* wv    = (const float*)d_in[10];
    const float* wo    = (const float*)d_in[11];
    const float* bo    = (const float*)d_in[12];
    const float* w_out = (const float*)d_in[13];
    const float* b_out = (const float*)d_in[14];
    float* out = (float*)d_out;

    float *bevf, *kv, *q, *k, *v, *attn, *fused;
    cudaGetSymbolAddress((void**)&bevf,  g_bev_feat);
    cudaGetSymbolAddress((void**)&kv,    g_kv);
    cudaGetSymbolAddress((void**)&q,     g_q);
    cudaGetSymbolAddress((void**)&k,     g_k);
    cudaGetSymbolAddress((void**)&v,     g_v);
    cudaGetSymbolAddress((void**)&attn,  g_attn);
    cudaGetSymbolAddress((void**)&fused, g_fused);

    dim3 cgrid(BT, 8, 4);
    conv3x3_relu_kernel<128, 144><<<cgrid, 256>>>(bev, ego, w_bev, b_bev, bevf, 128);
    conv3x3_relu_kernel<64, 64><<<cgrid, 256>>>(hd, nullptr, w_hd, b_hd, kv, 192);
    resize_kernel<<<(BT * 64 * HW) / 256, 256>>>(front, kv);
    qkv_kernel<<<dim3(64, 3), 256>>>(bevf, kv, wq, wk, wv, q, k, v);
    attention_kernel<<<dim3(8, 4, 8), 128>>>(q, k, v, attn);
    oproj_kernel<<<64, 256>>>(attn, wo, bo, fused);
    conv3x3_relu_kernel<128, 144><<<cgrid, 256>>>(fused, ego, w_out, b_out, out, 128);
}

// round 6
// speedup vs baseline: 1.0506x; 1.0230x over previous
#include <cuda_runtime.h>
#include <cuda_bf16.h>

// ---------------------------------------------------------------------------
// BEVHDMapFusionNet — round 4: occupancy-first restructure.
//  - attention: split-K x4 + merge, double-buffered K/V tiles
//  - gemm: 64x128 tiles (2x grid), 4x8 microtile
//  - conv: 8 oc/thread (2x grid)
// ---------------------------------------------------------------------------

#define BT 8
#define HW 1024

typedef unsigned long long u64;

__device__ __forceinline__ u64 pack2(float lo, float hi) {
    u64 r; asm("mov.b64 %0, {%1, %2};" : "=l"(r) : "f"(lo), "f"(hi)); return r;
}
__device__ __forceinline__ void unpack2(u64 v, float& lo, float& hi) {
    asm("mov.b64 {%0, %1}, %2;" : "=f"(lo), "=f"(hi) : "l"(v));
}
__device__ __forceinline__ void ffma2(u64& d, u64 a, u64 b) {
    asm("fma.rn.f32x2 %0, %1, %2, %0;" : "+l"(d) : "l"(a), "l"(b));
}
__device__ __forceinline__ u64 mul2(u64 a, u64 b) {
    u64 r; asm("mul.rn.f32x2 %0, %1, %2;" : "=l"(r) : "l"(a), "l"(b)); return r;
}
__device__ __forceinline__ u64 add2(u64 a, u64 b) {
    u64 r; asm("add.rn.f32x2 %0, %1, %2;" : "=l"(r) : "l"(a), "l"(b)); return r;
}

__device__ float g_bev_feat[BT * 128 * HW];  // NCHW
__device__ float g_kv[BT * 192 * HW];        // ch 0..127 hd_feat, 128..191 front
__device__ float g_q[BT * HW * 128];         // row-major [n][o]
__device__ float g_k[BT * HW * 128];
__device__ float g_v[BT * HW * 128];
__device__ float g_attn[BT * HW * 128];
__device__ float g_fused[BT * 128 * HW];     // NCHW
// attention split-K partials: [bt][h][chunk][d=32][n=1024], unnormalized O
__device__ float g_po[BT * 4 * 4 * 32 * 1024];
__device__ float2 g_pml[BT * 4 * 4 * 1024];  // (m, l) per row per chunk

// ---------------------------------------------------------------------------
// Direct 3x3 SAME conv + bias + relu. 256 threads = 32x * 8y pixels,
// 8 oc per thread (4 f32x2 accs). Grid: (BT, 16 oc-groups, 4 y-tiles) = 512.
// ---------------------------------------------------------------------------
template<int CIN_MAIN, int CIN_TOT>
__global__ void __launch_bounds__(256) conv3x3_relu_kernel(
    const float* __restrict__ in, const float* __restrict__ ego,
    const float* __restrict__ w, const float* __restrict__ bias,
    float* __restrict__ out, int out_ctot)
{
    __shared__ __align__(16) float s_in[16][10][34];  // ic x (8+2) x (32+2)
    __shared__ __align__(16) float s_w[16][9][8];     // [ic][k][oc]

    const int bt  = blockIdx.x;
    const int oc0 = blockIdx.y << 3;
    const int y0  = blockIdx.z << 3;
    const int tid = threadIdx.x;
    const int tx  = tid & 31, ty = tid >> 5;

    u64 acc2[4];
#pragma unroll
    for (int i = 0; i < 4; i++) acc2[i] = 0ull;

    for (int c0 = 0; c0 < CIN_TOT; c0 += 16) {
        for (int idx = tid; idx < 16 * 10 * 34; idx += 256) {
            int ic  = idx / 340;
            int rem = idx - ic * 340;
            int yy  = rem / 34, xx = rem - yy * 34;
            int gy  = y0 + yy - 1, gx = xx - 1;
            int c   = c0 + ic;
            float v = 0.f;
            if ((unsigned)gy < 32u && (unsigned)gx < 32u) {
                if (CIN_MAIN == CIN_TOT || c < CIN_MAIN)
                    v = in[((bt * CIN_MAIN + c) << 10) + (gy << 5) + gx];
                else
                    v = ego[(bt << 4) + (c - CIN_MAIN)];
            }
            s_in[ic][yy][xx] = v;
        }
        for (int idx = tid; idx < 16 * 9 * 8; idx += 256) {
            int oc  = idx & 7;
            int rem = idx >> 3;
            int ic  = rem / 9, k = rem - ic * 9;
            s_w[ic][k][oc] = w[((oc0 + oc) * CIN_TOT + c0 + ic) * 9 + k];
        }
        __syncthreads();

#pragma unroll 2
        for (int ic = 0; ic < 16; ic++) {
            float v[9];
#pragma unroll
            for (int ky = 0; ky < 3; ky++)
#pragma unroll
                for (int kx = 0; kx < 3; kx++)
                    v[ky * 3 + kx] = s_in[ic][ty + ky][tx + kx];
#pragma unroll
            for (int k = 0; k < 9; k++) {
                u64 vk2 = pack2(v[k], v[k]);
                const ulonglong2* wp = (const ulonglong2*)s_w[ic][k];
                ulonglong2 w01 = wp[0], w23 = wp[1];
                ffma2(acc2[0], vk2, w01.x); ffma2(acc2[1], vk2, w01.y);
                ffma2(acc2[2], vk2, w23.x); ffma2(acc2[3], vk2, w23.y);
            }
        }
        __syncthreads();
    }

    const int y = y0 + ty;
#pragma unroll
    for (int p = 0; p < 4; p++) {
        float f0, f1;
        unpack2(acc2[p], f0, f1);
        int oc = oc0 + 2 * p;
        out[((bt * out_ctot + oc) << 10) + (y << 5) + tx] =
            fmaxf(f0 + bias[oc], 0.f);
        out[((bt * out_ctot + oc + 1) << 10) + (y << 5) + tx] =
            fmaxf(f1 + bias[oc + 1], 0.f);
    }
}

// ---------------------------------------------------------------------------
// Bilinear 16x16 -> 32x32 resize (jax.image.resize semantics):
// index-clamped bilerp at src = dst*0.5 - 0.25. Writes ch 128..191 of g_kv.
// ---------------------------------------------------------------------------
__global__ void __launch_bounds__(256) resize_kernel(
    const float* __restrict__ front, float* __restrict__ kv)
{
    int idx = blockIdx.x * 256 + threadIdx.x;
    if (idx >= BT * 64 * HW) return;
    int x = idx & 31, y = (idx >> 5) & 31, c = (idx >> 10) & 63, bt = idx >> 16;
    float fy = y * 0.5f - 0.25f, fx = x * 0.5f - 0.25f;
    int y0 = (int)floorf(fy), x0 = (int)floorf(fx);
    float wy = fy - (float)y0, wx = fx - (float)x0;
    int y0c = max(y0, 0), y1c = min(y0 + 1, 15);
    int x0c = max(x0, 0), x1c = min(x0 + 1, 15);
    const float* base = &front[(bt * 64 + c) << 8];
    float v00 = base[(y0c << 4) + x0c], v01 = base[(y0c << 4) + x1c];
    float v10 = base[(y1c << 4) + x0c], v11 = base[(y1c << 4) + x1c];
    float v = (1.f - wy) * ((1.f - wx) * v00 + wx * v01)
            + wy * ((1.f - wx) * v10 + wx * v11);
    kv[((bt * 192 + 128 + c) << 10) + (y << 5) + x] = v;
}

// ---------------------------------------------------------------------------
// GEMM: out[bt][n][o] = sum_c A(c,n) * W[o][c].  64(m) x 128(n=o) tile,
// 256 threads, 4m x 8n microtile (f32x2 pairs along o).
// Grid: 128 mblocks (8192 rows / 64).
// ---------------------------------------------------------------------------
template<bool AROW, bool TOUT, int K>
__device__ __forceinline__ void gemm64_body(
    const float* __restrict__ A, const float* __restrict__ W,
    const float* __restrict__ bias, float* __restrict__ out)
{
    __shared__ __align__(16) float s_A[16][68];
    __shared__ __align__(16) float s_B[16][128];

    const int tid  = threadIdx.x;
    const int mblk = blockIdx.x;
    const int bt   = mblk >> 4;
    const int nloc = (mblk & 15) << 6;
    const int tm = tid & 15, tn = tid >> 4;
    const int m0 = tm << 2, o0 = tn << 3;

    u64 acc2[4][4];
#pragma unroll
    for (int i = 0; i < 4; i++)
#pragma unroll
        for (int j = 0; j < 4; j++) acc2[i][j] = 0ull;

    for (int c0 = 0; c0 < K; c0 += 16) {
        if (AROW) {
            for (int idx = tid; idx < 1024; idx += 256) {
                int kk = idx & 15, m = idx >> 4;
                s_A[kk][m] = A[(bt * 1024 + nloc + m) * K + c0 + kk];
            }
        } else {
            {
                int idx = tid;  // 256 float4 = 16kk x 64
                int kk = idx >> 4, j = idx & 15;
                float4 t = *(const float4*)&A[((bt * K + c0 + kk) << 10) + nloc + (j << 2)];
                *(float4*)&s_A[kk][j << 2] = t;
            }
        }
        for (int idx = tid; idx < 2048; idx += 256) {
            int o = idx & 127, kk = idx >> 7;
            s_B[kk][o] = W[o * K + c0 + kk];
        }
        __syncthreads();

#pragma unroll
        for (int kk = 0; kk < 16; kk++) {
            float4 a0 = *(const float4*)&s_A[kk][m0];
            ulonglong2 b01 = *(const ulonglong2*)&s_B[kk][o0];
            ulonglong2 b23 = *(const ulonglong2*)&s_B[kk][o0 + 4];
            u64 ap[4];
            ap[0] = pack2(a0.x, a0.x); ap[1] = pack2(a0.y, a0.y);
            ap[2] = pack2(a0.z, a0.z); ap[3] = pack2(a0.w, a0.w);
#pragma unroll
            for (int i = 0; i < 4; i++) {
                ffma2(acc2[i][0], ap[i], b01.x);
                ffma2(acc2[i][1], ap[i], b01.y);
                ffma2(acc2[i][2], ap[i], b23.x);
                ffma2(acc2[i][3], ap[i], b23.y);
            }
        }
        __syncthreads();
    }

    if (TOUT) {
        float f[4][8];
#pragma unroll
        for (int i = 0; i < 4; i++)
#pragma unroll
            for (int jp = 0; jp < 4; jp++)
                unpack2(acc2[i][jp], f[i][2 * jp], f[i][2 * jp + 1]);
#pragma unroll
        for (int j = 0; j < 8; j++) {
            float bb = bias ? bias[o0 + j] : 0.f;
            float4 t = {f[0][j] + bb, f[1][j] + bb, f[2][j] + bb, f[3][j] + bb};
            *(float4*)&out[((bt << 7) + o0 + j) * 1024 + nloc + m0] = t;
        }
    } else {
#pragma unroll
        for (int i = 0; i < 4; i++) {
            ulonglong2 t0 = {acc2[i][0], acc2[i][1]};
            ulonglong2 t1 = {acc2[i][2], acc2[i][3]};
            ulonglong2* op = (ulonglong2*)&out[(bt * 1024 + nloc + m0 + i) * 128 + o0];
            op[0] = t0; op[1] = t1;
        }
    }
}

__global__ void __launch_bounds__(256) qkv_kernel(
    const float* __restrict__ bevf, const float* __restrict__ kv,
    const float* __restrict__ wq, const float* __restrict__ wk,
    const float* __restrict__ wv,
    float* __restrict__ q, float* __restrict__ k, float* __restrict__ v)
{
    if (blockIdx.y == 0)      gemm64_body<false, false, 128>(bevf, wq, nullptr, q);
    else if (blockIdx.y == 1) gemm64_body<false, false, 192>(kv,   wk, nullptr, k);
    else                      gemm64_body<false, false, 192>(kv,   wv, nullptr, v);
}

__global__ void __launch_bounds__(256) oproj_kernel(
    const float* __restrict__ attn, const float* __restrict__ wo,
    const float* __restrict__ bo, float* __restrict__ fused)
{
    gemm64_body<true, true, 128>(attn, wo, bo, fused);
}

// ---------------------------------------------------------------------------
// Flash attention pass 1 (split-K x4). d=32, Nq=1024, each block covers a
// 128-query tile x one 256-row KV chunk. 128 threads = 1 query row each.
// Double-buffered K/V tiles staged through registers (1 sync per tile).
// Emits unnormalized O + (m, l) partials.
// Grid: (8 qtiles, 4 heads, 8 bt * 4 chunks) = 1024 blocks.
// ---------------------------------------------------------------------------
__global__ void __launch_bounds__(128) attention_part_kernel(
    const float* __restrict__ Q, const float* __restrict__ K,
    const float* __restrict__ V)
{
    __shared__ __align__(16) float sK[2][32][32];
    __shared__ __align__(16) float sV[2][32][32];
    const int qt = blockIdx.x, h = blockIdx.y;
    const int bt = blockIdx.z >> 2, ck = blockIdx.z & 3;
    const int r = threadIdx.x;
    const int n = (qt << 7) + r;
    const int kbase = ck << 8;
    const float scale = 0.17677669529663687f;   // 32^-0.5

    u64 q2[16];
    {
        u64 sc2 = pack2(scale, scale);
        const ulonglong2* qp = (const ulonglong2*)&Q[(bt * 1024 + n) * 128 + (h << 5)];
#pragma unroll
        for (int i = 0; i < 8; i++) {
            ulonglong2 t = qp[i];
            q2[2 * i]     = mul2(t.x, sc2);
            q2[2 * i + 1] = mul2(t.y, sc2);
        }
    }
    u64 o2[16];
#pragma unroll
    for (int i = 0; i < 16; i++) o2[i] = 0ull;
    float m_run = -1e30f, l_run = 0.f;

    // prologue: stage tile 0 into buffer 0
    {
        int kt = kbase;
#pragma unroll
        for (int ii = 0; ii < 2; ii++) {
            int i = r + (ii << 7);
            int kk = i >> 3, j = i & 7;
            ((float4*)sK[0][kk])[j] =
                ((const float4*)&K[((bt << 10) + kt + kk) * 128 + (h << 5)])[j];
            ((float4*)sV[0][kk])[j] =
                ((const float4*)&V[((bt << 10) + kt + kk) * 128 + (h << 5)])[j];
        }
    }
    __syncthreads();

    int buf = 0;
    for (int t = 0; t < 8; t++) {
        float4 pk[2], pv[2];
        if (t < 7) {
            int kt = kbase + ((t + 1) << 5);
#pragma unroll
            for (int ii = 0; ii < 2; ii++) {
                int i = r + (ii << 7);
                int kk = i >> 3, j = i & 7;
                pk[ii] = ((const float4*)&K[((bt << 10) + kt + kk) * 128 + (h << 5)])[j];
                pv[ii] = ((const float4*)&V[((bt << 10) + kt + kk) * 128 + (h << 5)])[j];
            }
        }

        float s[32];
#pragma unroll 4
        for (int kk = 0; kk < 32; kk++) {
            const ulonglong2* kp = (const ulonglong2*)sK[buf][kk];
            u64 acc0 = 0ull, acc1 = 0ull;
#pragma unroll
            for (int i = 0; i < 8; i++) {
                ulonglong2 t2 = kp[i];
                ffma2(acc0, q2[2 * i], t2.x);
                ffma2(acc1, q2[2 * i + 1], t2.y);
            }
            u64 accs = add2(acc0, acc1);
            float lo, hi;
            unpack2(accs, lo, hi);
            s[kk] = lo + hi;
        }
        float m_new = m_run;
#pragma unroll
        for (int kk = 0; kk < 32; kk++) m_new = fmaxf(m_new, s[kk]);
        float corr = __expf(m_run - m_new);
        float lad = 0.f;
#pragma unroll
        for (int kk = 0; kk < 32; kk++) { s[kk] = __expf(s[kk] - m_new); lad += s[kk]; }
        l_run = l_run * corr + lad;
        m_run = m_new;
        u64 corr2 = pack2(corr, corr);
#pragma unroll
        for (int i = 0; i < 16; i++) o2[i] = mul2(o2[i], corr2);
#pragma unroll 4
        for (int kk = 0; kk < 32; kk++) {
            const ulonglong2* vp = (const ulonglong2*)sV[buf][kk];
            u64 p2 = pack2(s[kk], s[kk]);
#pragma unroll
            for (int i = 0; i < 8; i++) {
                ulonglong2 t2 = vp[i];
                ffma2(o2[2 * i], p2, t2.x);
                ffma2(o2[2 * i + 1], p2, t2.y);
            }
        }

        if (t < 7) {
#pragma unroll
            for (int ii = 0; ii < 2; ii++) {
                int i = r + (ii << 7);
                int kk = i >> 3, j = i & 7;
                ((float4*)sK[buf ^ 1][kk])[j] = pk[ii];
                ((float4*)sV[buf ^ 1][kk])[j] = pv[ii];
            }
        }
        __syncthreads();
        buf ^= 1;
    }

    // store partials: po layout [bt][h][ck][d][n] (coalesced in n)
    float* po = g_po + ((((bt << 2) + h) << 2) + ck) * (32 * 1024) + n;
#pragma unroll
    for (int p = 0; p < 16; p++) {
        float f0, f1;
        unpack2(o2[p], f0, f1);
        po[(2 * p) * 1024]     = f0;
        po[(2 * p + 1) * 1024] = f1;
    }
    g_pml[((((bt << 2) + h) << 2) + ck) * 1024 + n] = make_float2(m_run, l_run);
}

// ---------------------------------------------------------------------------
// Merge split-K partials -> normalized attention output (row-major [n][128]).
// One thread per (bt, h, n) row. 32768 threads.
// ---------------------------------------------------------------------------
__global__ void __launch_bounds__(256) attention_merge_kernel(float* __restrict__ O)
{
    int idx = blockIdx.x * 256 + threadIdx.x;
    int n = idx & 1023, h = (idx >> 10) & 3, bt = idx >> 12;
    int rb = ((bt << 2) + h) << 2;

    float m[4], l[4];
#pragma unroll
    for (int c = 0; c < 4; c++) {
        float2 t = g_pml[(rb + c) * 1024 + n];
        m[c] = t.x; l[c] = t.y;
    }
    float ms = fmaxf(fmaxf(m[0], m[1]), fmaxf(m[2], m[3]));
    float w[4], ls = 0.f;
#pragma unroll
    for (int c = 0; c < 4; c++) { w[c] = __expf(m[c] - ms); ls += l[c] * w[c]; }
    float inv = 1.f / ls;

    float acc[32];
#pragma unroll
    for (int d = 0; d < 32; d++) acc[d] = 0.f;
#pragma unroll
    for (int c = 0; c < 4; c++) {
        const float* po = g_po + (rb + c) * (32 * 1024) + n;
        float wc = w[c];
#pragma unroll
        for (int d = 0; d < 32; d++)
            acc[d] = fmaf(wc, po[d * 1024], acc[d]);
    }
    float4* dst = (float4*)&O[(bt * 1024 + n) * 128 + (h << 5)];
#pragma unroll
    for (int j = 0; j < 8; j++) {
        float4 t = {acc[4 * j] * inv, acc[4 * j + 1] * inv,
                    acc[4 * j + 2] * inv, acc[4 * j + 3] * inv};
        dst[j] = t;
    }
}

// ---------------------------------------------------------------------------
extern "C" void kernel_launch(void* const* d_in, const int* in_sizes, int n_in,
                              void* d_out, int out_size)
{
    const float* bev   = (const float*)d_in[0];
    const float* hd    = (const float*)d_in[1];
    const float* ego   = (const float*)d_in[2];
    const float* front = (const float*)d_in[3];
    const float* w_bev = (const float*)d_in[4];
    const float* b_bev = (const float*)d_in[5];
    const float* w_hd  = (const float*)d_in[6];
    const float* b_hd  = (const float*)d_in[7];
    const float* wq    = (const float*)d_in[8];
    const float* wk    = (const float*)d_in[9];
    const float* wv    = (const float*)d_in[10];
    const float* wo    = (const float*)d_in[11];
    const float* bo    = (const float*)d_in[12];
    const float* w_out = (const float*)d_in[13];
    const float* b_out = (const float*)d_in[14];
    float* out = (float*)d_out;

    float *bevf, *kv, *q, *k, *v, *attn, *fused;
    cudaGetSymbolAddress((void**)&bevf,  g_bev_feat);
    cudaGetSymbolAddress((void**)&kv,    g_kv);
    cudaGetSymbolAddress((void**)&q,     g_q);
    cudaGetSymbolAddress((void**)&k,     g_k);
    cudaGetSymbolAddress((void**)&v,     g_v);
    cudaGetSymbolAddress((void**)&attn,  g_attn);
    cudaGetSymbolAddress((void**)&fused, g_fused);

    dim3 cgrid(BT, 16, 4);
    conv3x3_relu_kernel<128, 144><<<cgrid, 256>>>(bev, ego, w_bev, b_bev, bevf, 128);
    conv3x3_relu_kernel<64, 64><<<cgrid, 256>>>(hd, nullptr, w_hd, b_hd, kv, 192);
    resize_kernel<<<(BT * 64 * HW) / 256, 256>>>(front, kv);
    qkv_kernel<<<dim3(128, 3), 256>>>(bevf, kv, wq, wk, wv, q, k, v);
    attention_part_kernel<<<dim3(8, 4, 32), 128>>>(q, k, v);
    attention_merge_kernel<<<128, 256>>>(attn);
    oproj_kernel<<<128, 256>>>(attn, wo, bo, fused);
    conv3x3_relu_kernel<128, 144><<<cgrid, 256>>>(fused, ego, w_out, b_out, out, 128);
}

// round 7
// speedup vs baseline: 1.1029x; 1.0498x over previous
#include <cuda_runtime.h>
#include <cuda_bf16.h>

// ---------------------------------------------------------------------------
// BEVHDMapFusionNet — round 6: kill uncoalesced weight staging (32x L1 replay)
//  - all weights pre-transposed once per call into coalesced layouts
//  - GEMM: double-buffered K-loop (prefetch to regs), coalesced float4 staging
//  - conv: weights staged from [c][k][oc] layout (oc fastest)
// ---------------------------------------------------------------------------

#define BT 8
#define HW 1024

typedef unsigned long long u64;

__device__ __forceinline__ u64 pack2(float lo, float hi) {
    u64 r; asm("mov.b64 %0, {%1, %2};" : "=l"(r) : "f"(lo), "f"(hi)); return r;
}
__device__ __forceinline__ void unpack2(u64 v, float& lo, float& hi) {
    asm("mov.b64 {%0, %1}, %2;" : "=f"(lo), "=f"(hi) : "l"(v));
}
__device__ __forceinline__ void ffma2(u64& d, u64 a, u64 b) {
    asm("fma.rn.f32x2 %0, %1, %2, %0;" : "+l"(d) : "l"(a), "l"(b));
}
__device__ __forceinline__ u64 mul2(u64 a, u64 b) {
    u64 r; asm("mul.rn.f32x2 %0, %1, %2;" : "=l"(r) : "l"(a), "l"(b)); return r;
}
__device__ __forceinline__ u64 add2(u64 a, u64 b) {
    u64 r; asm("add.rn.f32x2 %0, %1, %2;" : "=l"(r) : "l"(a), "l"(b)); return r;
}

__device__ float g_bev_feat[BT * 128 * HW];  // NCHW
__device__ float g_kv[BT * 192 * HW];        // ch 0..127 hd_feat, 128..191 front
__device__ float g_q[BT * HW * 128];
__device__ float g_k[BT * HW * 128];
__device__ float g_v[BT * HW * 128];
__device__ float g_attn[BT * HW * 128];
__device__ float g_fused[BT * 128 * HW];
__device__ float g_po[BT * 4 * 4 * 32 * 1024];   // split-K partials [bt][h][ck][d][n]
__device__ float2 g_pml[BT * 4 * 4 * 1024];      // (m,l) per row per chunk

// transposed weights
__device__ float g_wq_t[128 * 128];   // [k][o]
__device__ float g_wk_t[192 * 128];
__device__ float g_wv_t[192 * 128];
__device__ float g_wo_t[128 * 128];
__device__ float g_wbev_t[144 * 9 * 128];  // [c][k][oc]
__device__ float g_whd_t[64 * 9 * 128];
__device__ float g_wout_t[144 * 9 * 128];

// ---------------------------------------------------------------------------
// weight transforms (run once per call; tiny)
// ---------------------------------------------------------------------------
__global__ void transform_gemm_w(const float* __restrict__ w,
                                 float* __restrict__ wt, int K)
{
    int idx = blockIdx.x * 256 + threadIdx.x;   // K*128
    if (idx >= K * 128) return;
    int o = idx & 127, k = idx >> 7;
    wt[k * 128 + o] = w[o * K + k];
}

__global__ void transform_conv_w(const float* __restrict__ w,
                                 float* __restrict__ wt, int CIN_TOT)
{
    int idx = blockIdx.x * 256 + threadIdx.x;   // CIN_TOT*9*128
    if (idx >= CIN_TOT * 9 * 128) return;
    int oc = idx & 127;
    int rem = idx >> 7;
    int k = rem % 9, c = rem / 9;
    wt[idx] = w[(oc * CIN_TOT + c) * 9 + k];
}

// ---------------------------------------------------------------------------
// Direct 3x3 SAME conv + bias + relu. 256 threads = 32x * 8y pixels,
// 8 oc per thread. Grid: (BT, 16 oc-groups, 4 y-tiles) = 512 blocks.
// Weights come pre-transposed: wt[(c*9 + k)*128 + oc]  (oc fastest).
// ---------------------------------------------------------------------------
template<int CIN_MAIN, int CIN_TOT>
__global__ void __launch_bounds__(256) conv3x3_relu_kernel(
    const float* __restrict__ in, const float* __restrict__ ego,
    const float* __restrict__ wt, const float* __restrict__ bias,
    float* __restrict__ out, int out_ctot)
{
    __shared__ __align__(16) float s_in[16][10][34];
    __shared__ __align__(16) float s_w[16][9][8];

    const int bt  = blockIdx.x;
    const int oc0 = blockIdx.y << 3;
    const int y0  = blockIdx.z << 3;
    const int tid = threadIdx.x;
    const int tx  = tid & 31, ty = tid >> 5;

    u64 acc2[4];
#pragma unroll
    for (int i = 0; i < 4; i++) acc2[i] = 0ull;

    for (int c0 = 0; c0 < CIN_TOT; c0 += 16) {
        for (int idx = tid; idx < 16 * 10 * 34; idx += 256) {
            int ic  = idx / 340;
            int rem = idx - ic * 340;
            int yy  = rem / 34, xx = rem - yy * 34;
            int gy  = y0 + yy - 1, gx = xx - 1;
            int c   = c0 + ic;
            float v = 0.f;
            if ((unsigned)gy < 32u && (unsigned)gx < 32u) {
                if (CIN_MAIN == CIN_TOT || c < CIN_MAIN)
                    v = in[((bt * CIN_MAIN + c) << 10) + (gy << 5) + gx];
                else
                    v = ego[(bt << 4) + (c - CIN_MAIN)];
            }
            s_in[ic][yy][xx] = v;
        }
        // coalesced weight staging: oc fastest (8 lanes, 32B segments)
        for (int idx = tid; idx < 16 * 9 * 8; idx += 256) {
            int oc  = idx & 7;
            int rem = idx >> 3;
            int k   = rem % 9, ic = rem / 9;
            s_w[ic][k][oc] = wt[((c0 + ic) * 9 + k) * 128 + oc0 + oc];
        }
        __syncthreads();

#pragma unroll 2
        for (int ic = 0; ic < 16; ic++) {
            float v[9];
#pragma unroll
            for (int ky = 0; ky < 3; ky++)
#pragma unroll
                for (int kx = 0; kx < 3; kx++)
                    v[ky * 3 + kx] = s_in[ic][ty + ky][tx + kx];
#pragma unroll
            for (int k = 0; k < 9; k++) {
                u64 vk2 = pack2(v[k], v[k]);
                const ulonglong2* wp = (const ulonglong2*)s_w[ic][k];
                ulonglong2 w01 = wp[0], w23 = wp[1];
                ffma2(acc2[0], vk2, w01.x); ffma2(acc2[1], vk2, w01.y);
                ffma2(acc2[2], vk2, w23.x); ffma2(acc2[3], vk2, w23.y);
            }
        }
        __syncthreads();
    }

    const int y = y0 + ty;
#pragma unroll
    for (int p = 0; p < 4; p++) {
        float f0, f1;
        unpack2(acc2[p], f0, f1);
        int oc = oc0 + 2 * p;
        out[((bt * out_ctot + oc) << 10) + (y << 5) + tx] =
            fmaxf(f0 + bias[oc], 0.f);
        out[((bt * out_ctot + oc + 1) << 10) + (y << 5) + tx] =
            fmaxf(f1 + bias[oc + 1], 0.f);
    }
}

// ---------------------------------------------------------------------------
// Bilinear 16x16 -> 32x32 resize (jax.image.resize: clamped bilerp,
// src = dst*0.5 - 0.25). Writes ch 128..191 of g_kv.
// ---------------------------------------------------------------------------
__global__ void __launch_bounds__(256) resize_kernel(
    const float* __restrict__ front, float* __restrict__ kv)
{
    int idx = blockIdx.x * 256 + threadIdx.x;
    if (idx >= BT * 64 * HW) return;
    int x = idx & 31, y = (idx >> 5) & 31, c = (idx >> 10) & 63, bt = idx >> 16;
    float fy = y * 0.5f - 0.25f, fx = x * 0.5f - 0.25f;
    int y0 = (int)floorf(fy), x0 = (int)floorf(fx);
    float wy = fy - (float)y0, wx = fx - (float)x0;
    int y0c = max(y0, 0), y1c = min(y0 + 1, 15);
    int x0c = max(x0, 0), x1c = min(x0 + 1, 15);
    const float* base = &front[(bt * 64 + c) << 8];
    float v00 = base[(y0c << 4) + x0c], v01 = base[(y0c << 4) + x1c];
    float v10 = base[(y1c << 4) + x0c], v11 = base[(y1c << 4) + x1c];
    float v = (1.f - wy) * ((1.f - wx) * v00 + wx * v01)
            + wy * ((1.f - wx) * v10 + wx * v11);
    kv[((bt * 192 + 128 + c) << 10) + (y << 5) + x] = v;
}

// ---------------------------------------------------------------------------
// GEMM: out[bt][n][o] = sum_c A(c,n) * Wt(c,o).  64(m) x 128(o) tile,
// 256 threads, 4m x 8o microtile. Wt is K-major [k][128] -> coalesced staging.
// Double-buffered K-loop: prefetch next chunk to regs during compute.
// ---------------------------------------------------------------------------
template<bool AROW, bool TOUT, int K>
__device__ __forceinline__ void gemm64_body(
    const float* __restrict__ A, const float* __restrict__ Wt,
    const float* __restrict__ bias, float* __restrict__ out)
{
    __shared__ __align__(16) float s_A[2][16][68];
    __shared__ __align__(16) float s_B[2][16][128];

    const int tid  = threadIdx.x;
    const int mblk = blockIdx.x;
    const int bt   = mblk >> 4;
    const int nloc = (mblk & 15) << 6;
    const int tm = tid & 15, tn = tid >> 4;
    const int m0 = tm << 2, o0 = tn << 3;
    const int NC = K / 16;

    // staging index precompute
    const int akk = tid >> 4, aj = tid & 15;          // A (NCHW path): 1 float4
    const int bkk = tid >> 4, bj = tid & 15;          // B: 2 float4 (kk, kk+... )

    u64 acc2[4][4];
#pragma unroll
    for (int i = 0; i < 4; i++)
#pragma unroll
        for (int j = 0; j < 4; j++) acc2[i][j] = 0ull;

    // prologue: stage chunk 0 into buffer 0
    if (AROW) {
        for (int idx = tid; idx < 1024; idx += 256) {
            int kk = idx & 15, m = idx >> 4;
            s_A[0][kk][m] = A[(bt * 1024 + nloc + m) * K + kk];
        }
    } else {
        float4 t = *(const float4*)&A[((bt * K + akk) << 10) + nloc + (aj << 2)];
        *(float4*)&s_A[0][akk][aj << 2] = t;
    }
    {
        float4 t0 = *(const float4*)&Wt[(bkk) * 128 + (bj << 2)];
        float4 t1 = *(const float4*)&Wt[(bkk) * 128 + 64 + (bj << 2)];
        *(float4*)&s_B[0][bkk][bj << 2] = t0;
        *(float4*)&s_B[0][bkk][64 + (bj << 2)] = t1;
    }
    __syncthreads();

    int buf = 0;
    for (int t = 0; t < NC; t++) {
        // prefetch next chunk into registers
        float4 pA, pB0, pB1;
        float pArow[4];
        if (t < NC - 1) {
            int c0 = (t + 1) << 4;
            if (AROW) {
#pragma unroll
                for (int ii = 0; ii < 4; ii++) {
                    int idx = tid + (ii << 8);
                    int kk = idx & 15, m = idx >> 4;
                    pArow[ii] = A[(bt * 1024 + nloc + m) * K + c0 + kk];
                }
            } else {
                pA = *(const float4*)&A[((bt * K + c0 + akk) << 10) + nloc + (aj << 2)];
            }
            pB0 = *(const float4*)&Wt[(c0 + bkk) * 128 + (bj << 2)];
            pB1 = *(const float4*)&Wt[(c0 + bkk) * 128 + 64 + (bj << 2)];
        }

        // compute on current buffer
#pragma unroll
        for (int kk = 0; kk < 16; kk++) {
            float4 a0 = *(const float4*)&s_A[buf][kk][m0];
            ulonglong2 b01 = *(const ulonglong2*)&s_B[buf][kk][o0];
            ulonglong2 b23 = *(const ulonglong2*)&s_B[buf][kk][o0 + 4];
            u64 ap[4];
            ap[0] = pack2(a0.x, a0.x); ap[1] = pack2(a0.y, a0.y);
            ap[2] = pack2(a0.z, a0.z); ap[3] = pack2(a0.w, a0.w);
#pragma unroll
            for (int i = 0; i < 4; i++) {
                ffma2(acc2[i][0], ap[i], b01.x);
                ffma2(acc2[i][1], ap[i], b01.y);
                ffma2(acc2[i][2], ap[i], b23.x);
                ffma2(acc2[i][3], ap[i], b23.y);
            }
        }

        // store prefetched chunk into the other buffer
        if (t < NC - 1) {
            int nb = buf ^ 1;
            if (AROW) {
#pragma unroll
                for (int ii = 0; ii < 4; ii++) {
                    int idx = tid + (ii << 8);
                    int kk = idx & 15, m = idx >> 4;
                    s_A[nb][kk][m] = pArow[ii];
                }
            } else {
                *(float4*)&s_A[nb][akk][aj << 2] = pA;
            }
            *(float4*)&s_B[nb][bkk][bj << 2] = pB0;
            *(float4*)&s_B[nb][bkk][64 + (bj << 2)] = pB1;
        }
        __syncthreads();
        buf ^= 1;
    }

    if (TOUT) {
        float f[4][8];
#pragma unroll
        for (int i = 0; i < 4; i++)
#pragma unroll
            for (int jp = 0; jp < 4; jp++)
                unpack2(acc2[i][jp], f[i][2 * jp], f[i][2 * jp + 1]);
#pragma unroll
        for (int j = 0; j < 8; j++) {
            float bb = bias ? bias[o0 + j] : 0.f;
            float4 t = {f[0][j] + bb, f[1][j] + bb, f[2][j] + bb, f[3][j] + bb};
            *(float4*)&out[((bt << 7) + o0 + j) * 1024 + nloc + m0] = t;
        }
    } else {
#pragma unroll
        for (int i = 0; i < 4; i++) {
            ulonglong2 t0 = {acc2[i][0], acc2[i][1]};
            ulonglong2 t1 = {acc2[i][2], acc2[i][3]};
            ulonglong2* op = (ulonglong2*)&out[(bt * 1024 + nloc + m0 + i) * 128 + o0];
            op[0] = t0; op[1] = t1;
        }
    }
}

__global__ void __launch_bounds__(256) qkv_kernel(
    const float* __restrict__ bevf, const float* __restrict__ kv,
    float* __restrict__ q, float* __restrict__ k, float* __restrict__ v)
{
    if (blockIdx.y == 0)      gemm64_body<false, false, 128>(bevf, g_wq_t, nullptr, q);
    else if (blockIdx.y == 1) gemm64_body<false, false, 192>(kv,   g_wk_t, nullptr, k);
    else                      gemm64_body<false, false, 192>(kv,   g_wv_t, nullptr, v);
}

__global__ void __launch_bounds__(256) oproj_kernel(
    const float* __restrict__ attn, const float* __restrict__ bo,
    float* __restrict__ fused)
{
    gemm64_body<true, true, 128>(attn, g_wo_t, bo, fused);
}

// ---------------------------------------------------------------------------
// Flash attention pass 1 (split-K x4), double-buffered K/V tiles.
// Grid: (8 qtiles, 4 heads, 8 bt * 4 chunks) = 1024 blocks of 128 threads.
// ---------------------------------------------------------------------------
__global__ void __launch_bounds__(128) attention_part_kernel(
    const float* __restrict__ Q, const float* __restrict__ K,
    const float* __restrict__ V)
{
    __shared__ __align__(16) float sK[2][32][32];
    __shared__ __align__(16) float sV[2][32][32];
    const int qt = blockIdx.x, h = blockIdx.y;
    const int bt = blockIdx.z >> 2, ck = blockIdx.z & 3;
    const int r = threadIdx.x;
    const int n = (qt << 7) + r;
    const int kbase = ck << 8;
    const float scale = 0.17677669529663687f;

    u64 q2[16];
    {
        u64 sc2 = pack2(scale, scale);
        const ulonglong2* qp = (const ulonglong2*)&Q[(bt * 1024 + n) * 128 + (h << 5)];
#pragma unroll
        for (int i = 0; i < 8; i++) {
            ulonglong2 t = qp[i];
            q2[2 * i]     = mul2(t.x, sc2);
            q2[2 * i + 1] = mul2(t.y, sc2);
        }
    }
    u64 o2[16];
#pragma unroll
    for (int i = 0; i < 16; i++) o2[i] = 0ull;
    float m_run = -1e30f, l_run = 0.f;

    {
        int kt = kbase;
#pragma unroll
        for (int ii = 0; ii < 2; ii++) {
            int i = r + (ii << 7);
            int kk = i >> 3, j = i & 7;
            ((float4*)sK[0][kk])[j] =
                ((const float4*)&K[((bt << 10) + kt + kk) * 128 + (h << 5)])[j];
            ((float4*)sV[0][kk])[j] =
                ((const float4*)&V[((bt << 10) + kt + kk) * 128 + (h << 5)])[j];
        }
    }
    __syncthreads();

    int buf = 0;
    for (int t = 0; t < 8; t++) {
        float4 pk[2], pv[2];
        if (t < 7) {
            int kt = kbase + ((t + 1) << 5);
#pragma unroll
            for (int ii = 0; ii < 2; ii++) {
                int i = r + (ii << 7);
                int kk = i >> 3, j = i & 7;
                pk[ii] = ((const float4*)&K[((bt << 10) + kt + kk) * 128 + (h << 5)])[j];
                pv[ii] = ((const float4*)&V[((bt << 10) + kt + kk) * 128 + (h << 5)])[j];
            }
        }

        float s[32];
#pragma unroll 4
        for (int kk = 0; kk < 32; kk++) {
            const ulonglong2* kp = (const ulonglong2*)sK[buf][kk];
            u64 acc0 = 0ull, acc1 = 0ull;
#pragma unroll
            for (int i = 0; i < 8; i++) {
                ulonglong2 t2 = kp[i];
                ffma2(acc0, q2[2 * i], t2.x);
                ffma2(acc1, q2[2 * i + 1], t2.y);
            }
            u64 accs = add2(acc0, acc1);
            float lo, hi;
            unpack2(accs, lo, hi);
            s[kk] = lo + hi;
        }
        float m_new = m_run;
#pragma unroll
        for (int kk = 0; kk < 32; kk++) m_new = fmaxf(m_new, s[kk]);
        float corr = __expf(m_run - m_new);
        float lad = 0.f;
#pragma unroll
        for (int kk = 0; kk < 32; kk++) { s[kk] = __expf(s[kk] - m_new); lad += s[kk]; }
        l_run = l_run * corr + lad;
        m_run = m_new;
        u64 corr2 = pack2(corr, corr);
#pragma unroll
        for (int i = 0; i < 16; i++) o2[i] = mul2(o2[i], corr2);
#pragma unroll 4
        for (int kk = 0; kk < 32; kk++) {
            const ulonglong2* vp = (const ulonglong2*)sV[buf][kk];
            u64 p2 = pack2(s[kk], s[kk]);
#pragma unroll
            for (int i = 0; i < 8; i++) {
                ulonglong2 t2 = vp[i];
                ffma2(o2[2 * i], p2, t2.x);
                ffma2(o2[2 * i + 1], p2, t2.y);
            }
        }

        if (t < 7) {
#pragma unroll
            for (int ii = 0; ii < 2; ii++) {
                int i = r + (ii << 7);
                int kk = i >> 3, j = i & 7;
                ((float4*)sK[buf ^ 1][kk])[j] = pk[ii];
                ((float4*)sV[buf ^ 1][kk])[j] = pv[ii];
            }
        }
        __syncthreads();
        buf ^= 1;
    }

    float* po = g_po + ((((bt << 2) + h) << 2) + ck) * (32 * 1024) + n;
#pragma unroll
    for (int p = 0; p < 16; p++) {
        float f0, f1;
        unpack2(o2[p], f0, f1);
        po[(2 * p) * 1024]     = f0;
        po[(2 * p + 1) * 1024] = f1;
    }
    g_pml[((((bt << 2) + h) << 2) + ck) * 1024 + n] = make_float2(m_run, l_run);
}

// ---------------------------------------------------------------------------
// Merge split-K partials -> normalized attention output (row-major [n][128]).
// ---------------------------------------------------------------------------
__global__ void __launch_bounds__(256) attention_merge_kernel(float* __restrict__ O)
{
    int idx = blockIdx.x * 256 + threadIdx.x;
    int n = idx & 1023, h = (idx >> 10) & 3, bt = idx >> 12;
    int rb = ((bt << 2) + h) << 2;

    float m[4], l[4];
#pragma unroll
    for (int c = 0; c < 4; c++) {
        float2 t = g_pml[(rb + c) * 1024 + n];
        m[c] = t.x; l[c] = t.y;
    }
    float ms = fmaxf(fmaxf(m[0], m[1]), fmaxf(m[2], m[3]));
    float w[4], ls = 0.f;
#pragma unroll
    for (int c = 0; c < 4; c++) { w[c] = __expf(m[c] - ms); ls += l[c] * w[c]; }
    float inv = 1.f / ls;

    float acc[32];
#pragma unroll
    for (int d = 0; d < 32; d++) acc[d] = 0.f;
#pragma unroll
    for (int c = 0; c < 4; c++) {
        const float* po = g_po + (rb + c) * (32 * 1024) + n;
        float wc = w[c];
#pragma unroll
        for (int d = 0; d < 32; d++)
            acc[d] = fmaf(wc, po[d * 1024], acc[d]);
    }
    float4* dst = (float4*)&O[(bt * 1024 + n) * 128 + (h << 5)];
#pragma unroll
    for (int j = 0; j < 8; j++) {
        float4 t = {acc[4 * j] * inv, acc[4 * j + 1] * inv,
                    acc[4 * j + 2] * inv, acc[4 * j + 3] * inv};
        dst[j] = t;
    }
}

// ---------------------------------------------------------------------------
extern "C" void kernel_launch(void* const* d_in, const int* in_sizes, int n_in,
                              void* d_out, int out_size)
{
    const float* bev   = (const float*)d_in[0];
    const float* hd    = (const float*)d_in[1];
    const float* ego   = (const float*)d_in[2];
    const float* front = (const float*)d_in[3];
    const float* w_bev = (const float*)d_in[4];
    const float* b_bev = (const float*)d_in[5];
    const float* w_hd  = (const float*)d_in[6];
    const float* b_hd  = (const float*)d_in[7];
    const float* wq    = (const float*)d_in[8];
    const float* wk    = (const float*)d_in[9];
    const float* wv    = (const float*)d_in[10];
    const float* wo    = (const float*)d_in[11];
    const float* bo    = (const float*)d_in[12];
    const float* w_out = (const float*)d_in[13];
    const float* b_out = (const float*)d_in[14];
    float* out = (float*)d_out;

    float *bevf, *kv, *q, *k, *v, *attn, *fused;
    float *wq_t, *wk_t, *wv_t, *wo_t, *wbev_t, *whd_t, *wout_t;
    cudaGetSymbolAddress((void**)&bevf,  g_bev_feat);
    cudaGetSymbolAddress((void**)&kv,    g_kv);
    cudaGetSymbolAddress((void**)&q,     g_q);
    cudaGetSymbolAddress((void**)&k,     g_k);
    cudaGetSymbolAddress((void**)&v,     g_v);
    cudaGetSymbolAddress((void**)&attn,  g_attn);
    cudaGetSymbolAddress((void**)&fused, g_fused);
    cudaGetSymbolAddress((void**)&wq_t,  g_wq_t);
    cudaGetSymbolAddress((void**)&wk_t,  g_wk_t);
    cudaGetSymbolAddress((void**)&wv_t,  g_wv_t);
    cudaGetSymbolAddress((void**)&wo_t,  g_wo_t);
    cudaGetSymbolAddress((void**)&wbev_t, g_wbev_t);
    cudaGetSymbolAddress((void**)&whd_t,  g_whd_t);
    cudaGetSymbolAddress((void**)&wout_t, g_wout_t);

    // weight transforms (tiny)
    transform_gemm_w<<<64, 256>>>(wq, wq_t, 128);
    transform_gemm_w<<<96, 256>>>(wk, wk_t, 192);
    transform_gemm_w<<<96, 256>>>(wv, wv_t, 192);
    transform_gemm_w<<<64, 256>>>(wo, wo_t, 128);
    transform_conv_w<<<648, 256>>>(w_bev, wbev_t, 144);
    transform_conv_w<<<288, 256>>>(w_hd,  whd_t,  64);
    transform_conv_w<<<648, 256>>>(w_out, wout_t, 144);

    dim3 cgrid(BT, 16, 4);
    conv3x3_relu_kernel<128, 144><<<cgrid, 256>>>(bev, ego, wbev_t, b_bev, bevf, 128);
    conv3x3_relu_kernel<64, 64><<<cgrid, 256>>>(hd, nullptr, whd_t, b_hd, kv, 192);
    resize_kernel<<<(BT * 64 * HW) / 256, 256>>>(front, kv);
    qkv_kernel<<<dim3(128, 3), 256>>>(bevf, kv, q, k, v);
    attention_part_kernel<<<dim3(8, 4, 32), 128>>>(q, k, v);
    attention_merge_kernel<<<128, 256>>>(attn);
    oproj_kernel<<<128, 256>>>(attn, bo, fused);
    conv3x3_relu_kernel<128, 144><<<cgrid, 256>>>(fused, ego, wout_t, b_out, out, 128);
}